// round 6
// baseline (speedup 1.0000x reference)
#include <cuda_runtime.h>
#include <cuda_fp16.h>
#include <math.h>
#include <stdint.h>

#define T_DIM 4096
#define B_DIM 16
#define C_DIM 512
#define M_DIM (T_DIM * B_DIM)      // 65536
#define H_DIM 8
#define K_DIM 7
#define PAD_L 3
#define NCHUNK 4
#define MCHUNK (M_DIM / NCHUNK)    // 16384 rows = 1024 t's

// ---------------- scratch (no allocations allowed) ----------------
__device__ __align__(16) float g_y[(size_t)M_DIM * C_DIM];     // GEMM out, 128 MB
__device__ __align__(16) __half g_wqh[C_DIM * C_DIM];          // quantized W, fp16 exact
__device__ float g_wsm[H_DIM * K_DIM];                         // softmaxed conv kernels

// ---------------- helpers ----------------
static __device__ __forceinline__ uint32_t smem_u32(const void* p) {
    uint32_t a;
    asm("{ .reg .u64 t; cvta.to.shared.u64 t, %1; cvt.u32.u64 %0, t; }" : "=r"(a) : "l"(p));
    return a;
}

#define CP_ASYNC16(dst, src) \
    asm volatile("cp.async.cg.shared.global [%0], [%1], 16;" :: "r"(dst), "l"(src) : "memory")
#define CP_COMMIT() asm volatile("cp.async.commit_group;" ::: "memory")
#define CP_WAIT1()  asm volatile("cp.async.wait_group 1;" ::: "memory")

#define LDSM_X4(r0, r1, r2, r3, a) \
    asm volatile("ldmatrix.sync.aligned.m8n8.x4.shared.b16 {%0,%1,%2,%3}, [%4];" \
        : "=r"(r0), "=r"(r1), "=r"(r2), "=r"(r3) : "r"(a))

#define MMA_F16(d, a, b0, b1) \
    asm volatile("mma.sync.aligned.m16n8k16.row.col.f32.f16.f16.f32 " \
        "{%0,%1,%2,%3}, {%4,%5,%6,%7}, {%8,%9}, {%0,%1,%2,%3};" \
        : "+f"((d)[0]), "+f"((d)[1]), "+f"((d)[2]), "+f"((d)[3]) \
        : "r"((a)[0]), "r"((a)[1]), "r"((a)[2]), "r"((a)[3]), "r"(b0), "r"(b1))

static __device__ __forceinline__ uint32_t packh2(float a, float b) {
    __half2 h = __floats2half2_rn(a, b);
    return *reinterpret_cast<uint32_t*>(&h);
}

// ---------------- prep: quantize W -> fp16 (exact powers of 2) + softmax ----------------
__global__ void prep_kernel(const float* __restrict__ W,
                            const float* __restrict__ conv_w) {
    int i = blockIdx.x * 256 + threadIdx.x;
    if (i < C_DIM * C_DIM) {
        float w = W[i];
        float a = fabsf(w) + 1e-12f;
        float e = rintf(log2f(a));
        float q = copysignf(exp2f(e), w);
        g_wqh[i] = __float2half((w == 0.0f) ? 0.0f : q);
    }
    if (blockIdx.x == 0 && threadIdx.x < H_DIM) {
        int h = threadIdx.x;
        float v[K_DIM];
        float m = -1e30f;
        #pragma unroll
        for (int k = 0; k < K_DIM; ++k) { v[k] = conv_w[h * K_DIM + k]; m = fmaxf(m, v[k]); }
        float s = 0.0f;
        #pragma unroll
        for (int k = 0; k < K_DIM; ++k) { v[k] = expf(v[k] - m); s += v[k]; }
        float inv = 1.0f / s;
        #pragma unroll
        for (int k = 0; k < K_DIM; ++k) g_wsm[h * K_DIM + k] = v[k] * inv;
    }
}

// ---------------- GEMM via mma.sync fp16, fused fp32->fp16 A conversion ----------------
// CTA tile 128x128, BK=64, 8 warps (4x2), warp tile 32x64, 3 stages, 2 CTAs/SM.
#define BM 128
#define BN 128
#define BK 64
#define ST_A 0
#define ST_B 16384
#define ST_SIZE 32768
#define SMEM_GEMM (3 * ST_SIZE)
#define KCH (C_DIM / BK)   // 8

__global__ void __launch_bounds__(256, 2) gemm_mma(const float* __restrict__ x,
                                                   const float* __restrict__ bias,
                                                   int mbase) {
    extern __shared__ char sm[];
    const uint32_t sb = smem_u32(sm);
    const int tid = threadIdx.x;
    const int lane = tid & 31;
    const int wid = tid >> 5;
    const int wm = wid & 3;          // warp row 0..3
    const int wn = wid >> 2;         // warp col 0..1
    const int m0 = mbase + blockIdx.y * BM;
    const int n0 = blockIdx.x * BN;

    float acc[2][8][4];
    #pragma unroll
    for (int i = 0; i < 2; ++i)
        #pragma unroll
        for (int j = 0; j < 8; ++j)
            #pragma unroll
            for (int q = 0; q < 4; ++q) acc[i][j][q] = 0.0f;

    // A: 128 rows x 16 float4 per stage = 2048 ops, 8/thread (LDG fp32 path)
    int ar[8], ag[8];
    #pragma unroll
    for (int t = 0; t < 8; ++t) { int idx = tid + t * 256; ar[t] = idx >> 4; ag[t] = idx & 15; }

    auto ldgA = [&](int kc, float4* regs) {
        const int kt = kc * BK;
        #pragma unroll
        for (int t = 0; t < 8; ++t)
            regs[t] = *(const float4*)&x[(size_t)(m0 + ar[t]) * C_DIM + kt + ag[t] * 4];
    };
    auto storeA = [&](int stage, const float4* regs) {
        const uint32_t base = sb + stage * ST_SIZE + ST_A;
        #pragma unroll
        for (int t = 0; t < 8; ++t) {
            uint32_t d = base + ar[t] * 128 + (((ag[t] >> 1) ^ (ar[t] & 7)) * 16) + (ag[t] & 1) * 8;
            uint2 v = make_uint2(packh2(regs[t].x, regs[t].y), packh2(regs[t].z, regs[t].w));
            asm volatile("st.shared.v2.b32 [%0], {%1, %2};" :: "r"(d), "r"(v.x), "r"(v.y) : "memory");
        }
    };
    auto issueB = [&](int stage, int kc) {
        const uint32_t base = sb + stage * ST_SIZE;
        const int kt = kc * BK;
        #pragma unroll
        for (int j = 0; j < 4; ++j) {
            int idx = tid + j * 256;
            int r = idx >> 3, c = idx & 7;
            const __half* s = g_wqh + (size_t)(n0 + r) * C_DIM + kt + c * 8;
            uint32_t d = base + ST_B + r * 128 + ((c ^ (r & 7)) * 16);
            CP_ASYNC16(d, s);
        }
    };

    float4 areg[8];
    ldgA(0, areg); storeA(0, areg);
    issueB(0, 0); CP_COMMIT();
    ldgA(1, areg); storeA(1, areg);
    issueB(1, 1); CP_COMMIT();

    const int arow  = wm * 32 + (lane & 15);
    const int axor  = arow & 7;
    const int ahalf = lane >> 4;
    const int bmidx = lane >> 3;
    const int brow0 = wn * 64 + ((bmidx >> 1) << 3) + (lane & 7);
    const int bxor  = lane & 7;
    const int bko   = bmidx & 1;

    #pragma unroll 1
    for (int i = 0; i < KCH; ++i) {
        const bool pf = (i + 2 < KCH);
        if (pf) ldgA(i + 2, areg);      // LDG before the barrier: latency hidden
        CP_WAIT1();
        __syncthreads();
        if (pf) {
            storeA((i + 2) % 3, areg);
            issueB((i + 2) % 3, i + 2);
        }
        CP_COMMIT();

        const uint32_t base = sb + (i % 3) * ST_SIZE;
        const uint32_t a_b = base + ST_A + arow * 128;
        const uint32_t b_b = base + ST_B + brow0 * 128;

        #pragma unroll
        for (int ks = 0; ks < 4; ++ks) {
            uint32_t coff = (((ks * 2 + ahalf) ^ axor) * 16);
            uint32_t ah[2][4], bb[4][4];
            #pragma unroll
            for (int mt = 0; mt < 2; ++mt)
                LDSM_X4(ah[mt][0], ah[mt][1], ah[mt][2], ah[mt][3], a_b + mt * 2048 + coff);
            uint32_t bcoff = (((ks * 2 + bko) ^ bxor) * 16);
            #pragma unroll
            for (int np = 0; np < 4; ++np)
                LDSM_X4(bb[np][0], bb[np][1], bb[np][2], bb[np][3], b_b + np * 2048 + bcoff);
            #pragma unroll
            for (int mt = 0; mt < 2; ++mt)
                #pragma unroll
                for (int nt = 0; nt < 8; ++nt) {
                    uint32_t b0 = bb[nt >> 1][(nt & 1) * 2];
                    uint32_t b1 = bb[nt >> 1][(nt & 1) * 2 + 1];
                    MMA_F16(acc[mt][nt], ah[mt], b0, b1);
                }
        }
    }

    // epilogue: bias + store
    const int r0 = lane >> 2;
    const int c2 = (lane & 3) * 2;
    #pragma unroll
    for (int mt = 0; mt < 2; ++mt) {
        int row = m0 + wm * 32 + mt * 16 + r0;
        #pragma unroll
        for (int nt = 0; nt < 8; ++nt) {
            int col = n0 + wn * 64 + nt * 8 + c2;
            float bx = __ldg(&bias[col]);
            float by = __ldg(&bias[col + 1]);
            float2 v0 = make_float2(acc[mt][nt][0] + bx, acc[mt][nt][1] + by);
            float2 v1 = make_float2(acc[mt][nt][2] + bx, acc[mt][nt][3] + by);
            *(float2*)&g_y[(size_t)row * C_DIM + col] = v0;
            *(float2*)&g_y[(size_t)(row + 8) * C_DIM + col] = v1;
        }
    }
}

// ---------------- depthwise conv along time (float4, 4-deep pipelined) ----------------
#define TCONV 32

static __device__ __forceinline__ void fma4(float4& o, float w, const float4& c) {
    o.x = fmaf(w, c.x, o.x); o.y = fmaf(w, c.y, o.y);
    o.z = fmaf(w, c.z, o.z); o.w = fmaf(w, c.w, o.w);
}

__global__ void __launch_bounds__(128) conv_kernel(float* __restrict__ out, int tbase) {
    const int q  = threadIdx.x;
    const int b  = blockIdx.y;
    const int t0 = tbase + blockIdx.x * TCONV;
    const int h  = q >> 4;

    float w[K_DIM];
    #pragma unroll
    for (int k = 0; k < K_DIM; ++k) w[k] = g_wsm[h * K_DIM + k];

    const float4* Y = (const float4*)g_y;
    float4* O = (float4*)out;
    const float4 z4 = make_float4(0.f, 0.f, 0.f, 0.f);

    float4 carry[6];
    #pragma unroll
    for (int j = 0; j < 6; ++j) {
        int tt = t0 - PAD_L + j;
        carry[j] = (tt >= 0) ? Y[(size_t)(tt * B_DIM + b) * 128 + q] : z4;
    }

    #pragma unroll
    for (int ch = 0; ch < TCONV / 4; ++ch) {
        const int tb = t0 + ch * 4;
        float4 cmb[10];
        #pragma unroll
        for (int j = 0; j < 6; ++j) cmb[j] = carry[j];
        #pragma unroll
        for (int j = 0; j < 4; ++j) {
            int tt = tb + PAD_L + j;
            cmb[6 + j] = (tt < T_DIM) ? Y[(size_t)(tt * B_DIM + b) * 128 + q] : z4;
        }
        #pragma unroll
        for (int i = 0; i < 4; ++i) {
            float4 o = z4;
            #pragma unroll
            for (int k = 0; k < K_DIM; ++k) fma4(o, w[k], cmb[i + k]);
            O[(size_t)((tb + i) * B_DIM + b) * 128 + q] = o;
        }
        #pragma unroll
        for (int j = 0; j < 6; ++j) carry[j] = cmb[4 + j];
    }
}

// ---------------- launch ----------------
extern "C" void kernel_launch(void* const* d_in, const int* in_sizes, int n_in,
                              void* d_out, int out_size) {
    const float* x       = (const float*)d_in[0];
    const float* shift_W = (const float*)d_in[1];
    const float* shift_b = (const float*)d_in[2];
    const float* weight  = (const float*)d_in[3];
    float* out = (float*)d_out;

    cudaFuncSetAttribute(gemm_mma, cudaFuncAttributeMaxDynamicSharedMemorySize, SMEM_GEMM);

    prep_kernel<<<(C_DIM * C_DIM + 255) / 256, 256>>>(shift_W, weight);

    // chunked launch order: g0 g1 c0 g2 c1 g3 c2 c3 (conv i needs y into chunk i+1's first 3 t's)
    dim3 ggrid(C_DIM / BN, MCHUNK / BM);         // (4, 128) per chunk
    dim3 cgrid((T_DIM / NCHUNK) / TCONV, B_DIM); // (32, 16) per chunk

    gemm_mma<<<ggrid, 256, SMEM_GEMM>>>(x, shift_b, 0 * MCHUNK);
    gemm_mma<<<ggrid, 256, SMEM_GEMM>>>(x, shift_b, 1 * MCHUNK);
    conv_kernel<<<cgrid, 128>>>(out, 0 * (T_DIM / NCHUNK));
    gemm_mma<<<ggrid, 256, SMEM_GEMM>>>(x, shift_b, 2 * MCHUNK);
    conv_kernel<<<cgrid, 128>>>(out, 1 * (T_DIM / NCHUNK));
    gemm_mma<<<ggrid, 256, SMEM_GEMM>>>(x, shift_b, 3 * MCHUNK);
    conv_kernel<<<cgrid, 128>>>(out, 2 * (T_DIM / NCHUNK));
    conv_kernel<<<cgrid, 128>>>(out, 3 * (T_DIM / NCHUNK));
}

// round 7
// speedup vs baseline: 1.5228x; 1.5228x over previous
#include <cuda_runtime.h>
#include <cuda_fp16.h>
#include <math.h>
#include <stdint.h>

#define T_DIM 4096
#define B_DIM 16
#define C_DIM 512
#define M_DIM (T_DIM * B_DIM)      // 65536
#define H_DIM 8
#define K_DIM 7
#define PAD_L 3

// ---------------- scratch (no allocations allowed) ----------------
__device__ __align__(16) __half g_yh[(size_t)M_DIM * C_DIM];   // GEMM out (fp16), 64 MB
__device__ __align__(16) __half g_wqh[C_DIM * C_DIM];          // quantized W, fp16 exact
__device__ float g_wsm[H_DIM * K_DIM];                         // softmaxed conv kernels

// ---------------- helpers ----------------
static __device__ __forceinline__ uint32_t smem_u32(const void* p) {
    uint32_t a;
    asm("{ .reg .u64 t; cvta.to.shared.u64 t, %1; cvt.u32.u64 %0, t; }" : "=r"(a) : "l"(p));
    return a;
}

#define CP_ASYNC16(dst, src) \
    asm volatile("cp.async.cg.shared.global [%0], [%1], 16;" :: "r"(dst), "l"(src) : "memory")
#define CP_COMMIT() asm volatile("cp.async.commit_group;" ::: "memory")
#define CP_WAIT1()  asm volatile("cp.async.wait_group 1;" ::: "memory")

#define LDSM_X4(r0, r1, r2, r3, a) \
    asm volatile("ldmatrix.sync.aligned.m8n8.x4.shared.b16 {%0,%1,%2,%3}, [%4];" \
        : "=r"(r0), "=r"(r1), "=r"(r2), "=r"(r3) : "r"(a))

#define MMA_F16(d, a, b0, b1) \
    asm volatile("mma.sync.aligned.m16n8k16.row.col.f32.f16.f16.f32 " \
        "{%0,%1,%2,%3}, {%4,%5,%6,%7}, {%8,%9}, {%0,%1,%2,%3};" \
        : "+f"((d)[0]), "+f"((d)[1]), "+f"((d)[2]), "+f"((d)[3]) \
        : "r"((a)[0]), "r"((a)[1]), "r"((a)[2]), "r"((a)[3]), "r"(b0), "r"(b1))

static __device__ __forceinline__ uint32_t packh2(float a, float b) {
    __half2 h = __floats2half2_rn(a, b);
    return *reinterpret_cast<uint32_t*>(&h);
}

// ---------------- prep: quantize W -> fp16 (exact powers of 2) + softmax ----------------
__global__ void prep_kernel(const float* __restrict__ W,
                            const float* __restrict__ conv_w) {
    int i = blockIdx.x * 256 + threadIdx.x;
    if (i < C_DIM * C_DIM) {
        float w = W[i];
        float a = fabsf(w) + 1e-12f;
        float e = rintf(log2f(a));
        float q = copysignf(exp2f(e), w);
        g_wqh[i] = __float2half((w == 0.0f) ? 0.0f : q);
    }
    if (blockIdx.x == 0 && threadIdx.x < H_DIM) {
        int h = threadIdx.x;
        float v[K_DIM];
        float m = -1e30f;
        #pragma unroll
        for (int k = 0; k < K_DIM; ++k) { v[k] = conv_w[h * K_DIM + k]; m = fmaxf(m, v[k]); }
        float s = 0.0f;
        #pragma unroll
        for (int k = 0; k < K_DIM; ++k) { v[k] = expf(v[k] - m); s += v[k]; }
        float inv = 1.0f / s;
        #pragma unroll
        for (int k = 0; k < K_DIM; ++k) g_wsm[h * K_DIM + k] = v[k] * inv;
    }
}

// ---------------- GEMM via mma.sync fp16, fused fp32->fp16 A conversion ----------------
// y[m,n] = sum_c x[m,c] * Wq[n,c] + b[n]   -> stored as fp16
// CTA tile 128x256, BK=64, 16 warps (4x4), warp tile 32x64, 3-stage.
#define BM 128
#define BN 256
#define BK 64
#define ST_A 0
#define ST_B 16384
#define ST_SIZE 49152
#define SMEM_GEMM (3 * ST_SIZE)
#define KCH (C_DIM / BK)   // 8

__global__ void __launch_bounds__(512, 1) gemm_mma(const float* __restrict__ x,
                                                   const float* __restrict__ bias) {
    extern __shared__ char sm[];
    const uint32_t sb = smem_u32(sm);
    const int tid = threadIdx.x;
    const int lane = tid & 31;
    const int wid = tid >> 5;
    const int wm = wid & 3;          // warp row 0..3
    const int wn = wid >> 2;         // warp col 0..3
    const int m0 = blockIdx.y * BM;
    const int n0 = blockIdx.x * BN;

    float acc[2][8][4];
    #pragma unroll
    for (int i = 0; i < 2; ++i)
        #pragma unroll
        for (int j = 0; j < 8; ++j)
            #pragma unroll
            for (int q = 0; q < 4; ++q) acc[i][j][q] = 0.0f;

    // A: 128 rows x 16 float4 per stage = 2048 ops, 4/thread (LDG fp32 path)
    int ar[4], ag[4];
    #pragma unroll
    for (int t = 0; t < 4; ++t) { int idx = tid + t * 512; ar[t] = idx >> 4; ag[t] = idx & 15; }

    auto ldgA = [&](int kc, float4* regs) {
        const int kt = kc * BK;
        #pragma unroll
        for (int t = 0; t < 4; ++t)
            regs[t] = *(const float4*)&x[(size_t)(m0 + ar[t]) * C_DIM + kt + ag[t] * 4];
    };
    auto storeA = [&](int stage, const float4* regs) {
        const uint32_t base = sb + stage * ST_SIZE + ST_A;
        #pragma unroll
        for (int t = 0; t < 4; ++t) {
            uint32_t d = base + ar[t] * 128 + (((ag[t] >> 1) ^ (ar[t] & 7)) * 16) + (ag[t] & 1) * 8;
            uint2 v = make_uint2(packh2(regs[t].x, regs[t].y), packh2(regs[t].z, regs[t].w));
            asm volatile("st.shared.v2.b32 [%0], {%1, %2};" :: "r"(d), "r"(v.x), "r"(v.y) : "memory");
        }
    };
    auto issueB = [&](int stage, int kc) {
        const uint32_t base = sb + stage * ST_SIZE;
        const int kt = kc * BK;
        #pragma unroll
        for (int j = 0; j < 4; ++j) {
            int idx = tid + j * 512;
            int r = idx >> 3, c = idx & 7;
            const __half* s = g_wqh + (size_t)(n0 + r) * C_DIM + kt + c * 8;
            uint32_t d = base + ST_B + r * 128 + ((c ^ (r & 7)) * 16);
            CP_ASYNC16(d, s);
        }
    };

    float4 areg[4];
    ldgA(0, areg); storeA(0, areg);
    issueB(0, 0); CP_COMMIT();
    ldgA(1, areg); storeA(1, areg);
    issueB(1, 1); CP_COMMIT();

    const int arow  = wm * 32 + (lane & 15);
    const int axor  = arow & 7;
    const int ahalf = lane >> 4;
    const int bmidx = lane >> 3;
    const int brow0 = wn * 64 + ((bmidx >> 1) << 3) + (lane & 7);
    const int bxor  = lane & 7;
    const int bko   = bmidx & 1;

    #pragma unroll 1
    for (int i = 0; i < KCH; ++i) {
        const bool pf = (i + 2 < KCH);
        if (pf) ldgA(i + 2, areg);      // LDG before the barrier: latency hidden
        CP_WAIT1();
        __syncthreads();
        if (pf) {
            storeA((i + 2) % 3, areg);
            issueB((i + 2) % 3, i + 2);
        }
        CP_COMMIT();

        const uint32_t base = sb + (i % 3) * ST_SIZE;
        const uint32_t a_b = base + ST_A + arow * 128;
        const uint32_t b_b = base + ST_B + brow0 * 128;

        #pragma unroll
        for (int ks = 0; ks < 4; ++ks) {
            uint32_t coff = (((ks * 2 + ahalf) ^ axor) * 16);
            uint32_t ah[2][4], bb[4][4];
            #pragma unroll
            for (int mt = 0; mt < 2; ++mt)
                LDSM_X4(ah[mt][0], ah[mt][1], ah[mt][2], ah[mt][3], a_b + mt * 2048 + coff);
            uint32_t bcoff = (((ks * 2 + bko) ^ bxor) * 16);
            #pragma unroll
            for (int np = 0; np < 4; ++np)
                LDSM_X4(bb[np][0], bb[np][1], bb[np][2], bb[np][3], b_b + np * 2048 + bcoff);
            #pragma unroll
            for (int mt = 0; mt < 2; ++mt)
                #pragma unroll
                for (int nt = 0; nt < 8; ++nt) {
                    uint32_t b0 = bb[nt >> 1][(nt & 1) * 2];
                    uint32_t b1 = bb[nt >> 1][(nt & 1) * 2 + 1];
                    MMA_F16(acc[mt][nt], ah[mt], b0, b1);
                }
        }
    }

    // epilogue: bias + fp16 store
    const int r0 = lane >> 2;
    const int c2 = (lane & 3) * 2;
    #pragma unroll
    for (int mt = 0; mt < 2; ++mt) {
        int row = m0 + wm * 32 + mt * 16 + r0;
        #pragma unroll
        for (int nt = 0; nt < 8; ++nt) {
            int col = n0 + wn * 64 + nt * 8 + c2;
            float bx = __ldg(&bias[col]);
            float by = __ldg(&bias[col + 1]);
            uint32_t v0 = packh2(acc[mt][nt][0] + bx, acc[mt][nt][1] + by);
            uint32_t v1 = packh2(acc[mt][nt][2] + bx, acc[mt][nt][3] + by);
            *(uint32_t*)&g_yh[(size_t)row * C_DIM + col] = v0;
            *(uint32_t*)&g_yh[(size_t)(row + 8) * C_DIM + col] = v1;
        }
    }
}

// ---------------- depthwise conv along time (fp16 in, fp32 out) ----------------
#define TCONV 32

static __device__ __forceinline__ void fma4(float4& o, float w, const float4& c) {
    o.x = fmaf(w, c.x, o.x); o.y = fmaf(w, c.y, o.y);
    o.z = fmaf(w, c.z, o.z); o.w = fmaf(w, c.w, o.w);
}
static __device__ __forceinline__ float4 ld_y4(const uint2* Y, size_t idx) {
    uint2 raw = __ldg(&Y[idx]);
    __half2 h0 = *reinterpret_cast<__half2*>(&raw.x);
    __half2 h1 = *reinterpret_cast<__half2*>(&raw.y);
    float2 f0 = __half22float2(h0);
    float2 f1 = __half22float2(h1);
    return make_float4(f0.x, f0.y, f1.x, f1.y);
}

__global__ void __launch_bounds__(128) conv_kernel(float* __restrict__ out) {
    const int q  = threadIdx.x;            // channel group: 4 channels q*4..q*4+3
    const int b  = blockIdx.y;
    const int t0 = blockIdx.x * TCONV;
    const int h  = q >> 4;                 // (q*4)/64

    float w[K_DIM];
    #pragma unroll
    for (int k = 0; k < K_DIM; ++k) w[k] = g_wsm[h * K_DIM + k];

    const uint2* Y = (const uint2*)g_yh;   // index: (t*16+b)*128 + q -> 4 halves
    float4* O = (float4*)out;
    const float4 z4 = make_float4(0.f, 0.f, 0.f, 0.f);

    float4 carry[6];
    #pragma unroll
    for (int j = 0; j < 6; ++j) {
        int tt = t0 - PAD_L + j;
        carry[j] = (tt >= 0) ? ld_y4(Y, (size_t)(tt * B_DIM + b) * 128 + q) : z4;
    }

    #pragma unroll
    for (int ch = 0; ch < TCONV / 4; ++ch) {
        const int tb = t0 + ch * 4;
        float4 cmb[10];
        #pragma unroll
        for (int j = 0; j < 6; ++j) cmb[j] = carry[j];
        #pragma unroll
        for (int j = 0; j < 4; ++j) {
            int tt = tb + PAD_L + j;
            cmb[6 + j] = (tt < T_DIM) ? ld_y4(Y, (size_t)(tt * B_DIM + b) * 128 + q) : z4;
        }
        #pragma unroll
        for (int i = 0; i < 4; ++i) {
            float4 o = z4;
            #pragma unroll
            for (int k = 0; k < K_DIM; ++k) fma4(o, w[k], cmb[i + k]);
            O[(size_t)((tb + i) * B_DIM + b) * 128 + q] = o;
        }
        #pragma unroll
        for (int j = 0; j < 6; ++j) carry[j] = cmb[4 + j];
    }
}

// ---------------- launch ----------------
extern "C" void kernel_launch(void* const* d_in, const int* in_sizes, int n_in,
                              void* d_out, int out_size) {
    const float* x       = (const float*)d_in[0];
    const float* shift_W = (const float*)d_in[1];
    const float* shift_b = (const float*)d_in[2];
    const float* weight  = (const float*)d_in[3];
    float* out = (float*)d_out;

    cudaFuncSetAttribute(gemm_mma, cudaFuncAttributeMaxDynamicSharedMemorySize, SMEM_GEMM);

    prep_kernel<<<(C_DIM * C_DIM + 255) / 256, 256>>>(shift_W, weight);

    dim3 ggrid(C_DIM / BN, M_DIM / BM);   // (2, 512)
    gemm_mma<<<ggrid, 512, SMEM_GEMM>>>(x, shift_b);

    dim3 cgrid(T_DIM / TCONV, B_DIM);     // (128, 16)
    conv_kernel<<<cgrid, 128>>>(out);
}

// round 8
// speedup vs baseline: 1.6111x; 1.0580x over previous
#include <cuda_runtime.h>
#include <cuda_fp16.h>
#include <math.h>
#include <stdint.h>

#define T_DIM 4096
#define B_DIM 16
#define C_DIM 512
#define M_DIM (T_DIM * B_DIM)      // 65536
#define H_DIM 8
#define K_DIM 7
#define PAD_L 3

// ---------------- scratch (no allocations allowed) ----------------
__device__ __align__(16) __half g_yh[(size_t)M_DIM * C_DIM];   // GEMM out (fp16), 64 MB
__device__ __align__(16) __half g_wqh[C_DIM * C_DIM];          // quantized W, fp16 exact
__device__ float g_wsm[H_DIM * K_DIM];                         // softmaxed conv kernels

// ---------------- helpers ----------------
static __device__ __forceinline__ uint32_t smem_u32(const void* p) {
    uint32_t a;
    asm("{ .reg .u64 t; cvta.to.shared.u64 t, %1; cvt.u32.u64 %0, t; }" : "=r"(a) : "l"(p));
    return a;
}

#define CP_ASYNC16(dst, src) \
    asm volatile("cp.async.cg.shared.global [%0], [%1], 16;" :: "r"(dst), "l"(src) : "memory")
#define CP_COMMIT() asm volatile("cp.async.commit_group;" ::: "memory")
#define CP_WAIT1()  asm volatile("cp.async.wait_group 1;" ::: "memory")

#define LDSM_X4(r0, r1, r2, r3, a) \
    asm volatile("ldmatrix.sync.aligned.m8n8.x4.shared.b16 {%0,%1,%2,%3}, [%4];" \
        : "=r"(r0), "=r"(r1), "=r"(r2), "=r"(r3) : "r"(a))

#define MMA_F16(d, a, b0, b1) \
    asm volatile("mma.sync.aligned.m16n8k16.row.col.f32.f16.f16.f32 " \
        "{%0,%1,%2,%3}, {%4,%5,%6,%7}, {%8,%9}, {%0,%1,%2,%3};" \
        : "+f"((d)[0]), "+f"((d)[1]), "+f"((d)[2]), "+f"((d)[3]) \
        : "r"((a)[0]), "r"((a)[1]), "r"((a)[2]), "r"((a)[3]), "r"(b0), "r"(b1))

static __device__ __forceinline__ uint32_t packh2(float a, float b) {
    __half2 h = __floats2half2_rn(a, b);
    return *reinterpret_cast<uint32_t*>(&h);
}

// ---------------- prep: quantize W -> fp16 (exact powers of 2) + softmax ----------------
__global__ void prep_kernel(const float* __restrict__ W,
                            const float* __restrict__ conv_w) {
    int i = blockIdx.x * 256 + threadIdx.x;
    if (i < C_DIM * C_DIM) {
        float w = W[i];
        float a = fabsf(w) + 1e-12f;
        float e = rintf(log2f(a));
        float q = copysignf(exp2f(e), w);
        g_wqh[i] = __float2half((w == 0.0f) ? 0.0f : q);
    }
    if (blockIdx.x == 0 && threadIdx.x < H_DIM) {
        int h = threadIdx.x;
        float v[K_DIM];
        float m = -1e30f;
        #pragma unroll
        for (int k = 0; k < K_DIM; ++k) { v[k] = conv_w[h * K_DIM + k]; m = fmaxf(m, v[k]); }
        float s = 0.0f;
        #pragma unroll
        for (int k = 0; k < K_DIM; ++k) { v[k] = expf(v[k] - m); s += v[k]; }
        float inv = 1.0f / s;
        #pragma unroll
        for (int k = 0; k < K_DIM; ++k) g_wsm[h * K_DIM + k] = v[k] * inv;
    }
}

// ---------------- GEMM via mma.sync fp16, fused fp32->fp16 A conversion ----------------
// CTA tile 128x256, BK=64, 8 warps (2 wm x 4 wn), warp tile 64x64, 3-stage.
#define BM 128
#define BN 256
#define BK 64
#define ST_A 0
#define ST_B 16384
#define ST_SIZE 49152
#define SMEM_GEMM (3 * ST_SIZE)
#define KCH (C_DIM / BK)   // 8

__global__ void __launch_bounds__(256, 1) gemm_mma(const float* __restrict__ x,
                                                   const float* __restrict__ bias) {
    extern __shared__ char sm[];
    const uint32_t sb = smem_u32(sm);
    const int tid = threadIdx.x;
    const int lane = tid & 31;
    const int wid = tid >> 5;
    const int wm = wid & 1;          // warp row 0..1 (64 M rows each)
    const int wn = wid >> 1;         // warp col 0..3 (64 N cols each)
    const int m0 = blockIdx.y * BM;
    const int n0 = blockIdx.x * BN;

    float acc[4][8][4];
    #pragma unroll
    for (int i = 0; i < 4; ++i)
        #pragma unroll
        for (int j = 0; j < 8; ++j)
            #pragma unroll
            for (int q = 0; q < 4; ++q) acc[i][j][q] = 0.0f;

    // A: 128 rows x 16 float4 per stage = 2048 ops, 8/thread (LDG fp32 path)
    int ar[8], ag[8];
    #pragma unroll
    for (int t = 0; t < 8; ++t) { int idx = tid + t * 256; ar[t] = idx >> 4; ag[t] = idx & 15; }

    auto ldgA = [&](int kc, float4* regs) {
        const int kt = kc * BK;
        #pragma unroll
        for (int t = 0; t < 8; ++t)
            regs[t] = *(const float4*)&x[(size_t)(m0 + ar[t]) * C_DIM + kt + ag[t] * 4];
    };
    auto storeA = [&](int stage, const float4* regs) {
        const uint32_t base = sb + stage * ST_SIZE + ST_A;
        #pragma unroll
        for (int t = 0; t < 8; ++t) {
            uint32_t d = base + ar[t] * 128 + (((ag[t] >> 1) ^ (ar[t] & 7)) * 16) + (ag[t] & 1) * 8;
            uint2 v = make_uint2(packh2(regs[t].x, regs[t].y), packh2(regs[t].z, regs[t].w));
            asm volatile("st.shared.v2.b32 [%0], {%1, %2};" :: "r"(d), "r"(v.x), "r"(v.y) : "memory");
        }
    };
    auto issueB = [&](int stage, int kc) {
        const uint32_t base = sb + stage * ST_SIZE;
        const int kt = kc * BK;
        #pragma unroll
        for (int j = 0; j < 8; ++j) {
            int idx = tid + j * 256;
            int r = idx >> 3, c = idx & 7;
            const __half* s = g_wqh + (size_t)(n0 + r) * C_DIM + kt + c * 8;
            uint32_t d = base + ST_B + r * 128 + ((c ^ (r & 7)) * 16);
            CP_ASYNC16(d, s);
        }
    };

    float4 areg[8];
    ldgA(0, areg); storeA(0, areg);
    issueB(0, 0); CP_COMMIT();
    ldgA(1, areg); storeA(1, areg);
    issueB(1, 1); CP_COMMIT();

    // ldmatrix per-lane geometry
    const int arow  = wm * 64 + (lane & 15);   // + mt*16 below
    const int axor  = arow & 7;
    const int ahalf = lane >> 4;
    const int bmidx = lane >> 3;
    const int brow0 = wn * 64 + ((bmidx >> 1) << 3) + (lane & 7);
    const int bxor  = lane & 7;
    const int bko   = bmidx & 1;

    #pragma unroll 1
    for (int i = 0; i < KCH; ++i) {
        const bool pf = (i + 2 < KCH);
        if (pf) ldgA(i + 2, areg);      // LDG issued before the wait: full MMA phase to land
        CP_WAIT1();
        __syncthreads();

        const uint32_t base = sb + (i % 3) * ST_SIZE;
        const uint32_t a_b = base + ST_A + arow * 128;
        const uint32_t b_b = base + ST_B + brow0 * 128;

        #pragma unroll
        for (int ks = 0; ks < 4; ++ks) {
            uint32_t coff = (((ks * 2 + ahalf) ^ axor) * 16);
            uint32_t ah[4][4], bb[4][4];
            #pragma unroll
            for (int mt = 0; mt < 4; ++mt)
                LDSM_X4(ah[mt][0], ah[mt][1], ah[mt][2], ah[mt][3], a_b + mt * 2048 + coff);
            uint32_t bcoff = (((ks * 2 + bko) ^ bxor) * 16);
            #pragma unroll
            for (int np = 0; np < 4; ++np)
                LDSM_X4(bb[np][0], bb[np][1], bb[np][2], bb[np][3], b_b + np * 2048 + bcoff);
            #pragma unroll
            for (int mt = 0; mt < 4; ++mt)
                #pragma unroll
                for (int nt = 0; nt < 8; ++nt) {
                    uint32_t b0 = bb[nt >> 1][(nt & 1) * 2];
                    uint32_t b1 = bb[nt >> 1][(nt & 1) * 2 + 1];
                    MMA_F16(acc[mt][nt], ah[mt], b0, b1);
                }
        }

        if (pf) {
            storeA((i + 2) % 3, areg);   // after MMA phase: LDG long since complete
            issueB((i + 2) % 3, i + 2);
        }
        CP_COMMIT();
    }

    // epilogue: bias + fp16 store
    const int r0 = lane >> 2;
    const int c2 = (lane & 3) * 2;
    #pragma unroll
    for (int mt = 0; mt < 4; ++mt) {
        int row = m0 + wm * 64 + mt * 16 + r0;
        #pragma unroll
        for (int nt = 0; nt < 8; ++nt) {
            int col = n0 + wn * 64 + nt * 8 + c2;
            float bx = __ldg(&bias[col]);
            float by = __ldg(&bias[col + 1]);
            uint32_t v0 = packh2(acc[mt][nt][0] + bx, acc[mt][nt][1] + by);
            uint32_t v1 = packh2(acc[mt][nt][2] + bx, acc[mt][nt][3] + by);
            *(uint32_t*)&g_yh[(size_t)row * C_DIM + col] = v0;
            *(uint32_t*)&g_yh[(size_t)(row + 8) * C_DIM + col] = v1;
        }
    }
}

// ---------------- depthwise conv along time (fp16 in, fp32 out) ----------------
#define TCONV 32

static __device__ __forceinline__ void fma4(float4& o, float w, const float4& c) {
    o.x = fmaf(w, c.x, o.x); o.y = fmaf(w, c.y, o.y);
    o.z = fmaf(w, c.z, o.z); o.w = fmaf(w, c.w, o.w);
}
static __device__ __forceinline__ float4 ld_y4(const uint2* Y, size_t idx) {
    uint2 raw = __ldg(&Y[idx]);
    __half2 h0 = *reinterpret_cast<__half2*>(&raw.x);
    __half2 h1 = *reinterpret_cast<__half2*>(&raw.y);
    float2 f0 = __half22float2(h0);
    float2 f1 = __half22float2(h1);
    return make_float4(f0.x, f0.y, f1.x, f1.y);
}

__global__ void __launch_bounds__(128) conv_kernel(float* __restrict__ out) {
    const int q  = threadIdx.x;            // channel group: 4 channels q*4..q*4+3
    const int b  = blockIdx.y;
    const int t0 = blockIdx.x * TCONV;
    const int h  = q >> 4;                 // (q*4)/64

    float w[K_DIM];
    #pragma unroll
    for (int k = 0; k < K_DIM; ++k) w[k] = g_wsm[h * K_DIM + k];

    const uint2* Y = (const uint2*)g_yh;   // index: (t*16+b)*128 + q -> 4 halves
    float4* O = (float4*)out;
    const float4 z4 = make_float4(0.f, 0.f, 0.f, 0.f);

    float4 carry[6];
    #pragma unroll
    for (int j = 0; j < 6; ++j) {
        int tt = t0 - PAD_L + j;
        carry[j] = (tt >= 0) ? ld_y4(Y, (size_t)(tt * B_DIM + b) * 128 + q) : z4;
    }

    #pragma unroll
    for (int ch = 0; ch < TCONV / 4; ++ch) {
        const int tb = t0 + ch * 4;
        float4 cmb[10];
        #pragma unroll
        for (int j = 0; j < 6; ++j) cmb[j] = carry[j];
        #pragma unroll
        for (int j = 0; j < 4; ++j) {
            int tt = tb + PAD_L + j;
            cmb[6 + j] = (tt < T_DIM) ? ld_y4(Y, (size_t)(tt * B_DIM + b) * 128 + q) : z4;
        }
        #pragma unroll
        for (int i = 0; i < 4; ++i) {
            float4 o = z4;
            #pragma unroll
            for (int k = 0; k < K_DIM; ++k) fma4(o, w[k], cmb[i + k]);
            O[(size_t)((tb + i) * B_DIM + b) * 128 + q] = o;
        }
        #pragma unroll
        for (int j = 0; j < 6; ++j) carry[j] = cmb[4 + j];
    }
}

// ---------------- launch ----------------
extern "C" void kernel_launch(void* const* d_in, const int* in_sizes, int n_in,
                              void* d_out, int out_size) {
    const float* x       = (const float*)d_in[0];
    const float* shift_W = (const float*)d_in[1];
    const float* shift_b = (const float*)d_in[2];
    const float* weight  = (const float*)d_in[3];
    float* out = (float*)d_out;

    cudaFuncSetAttribute(gemm_mma, cudaFuncAttributeMaxDynamicSharedMemorySize, SMEM_GEMM);

    prep_kernel<<<(C_DIM * C_DIM + 255) / 256, 256>>>(shift_W, weight);

    dim3 ggrid(C_DIM / BN, M_DIM / BM);   // (2, 512)
    gemm_mma<<<ggrid, 256, SMEM_GEMM>>>(x, shift_b);

    dim3 cgrid(T_DIM / TCONV, B_DIM);     // (128, 16)
    conv_kernel<<<cgrid, 128>>>(out);
}

// round 9
// speedup vs baseline: 1.6747x; 1.0395x over previous
#include <cuda_runtime.h>
#include <cuda_fp16.h>
#include <math.h>
#include <stdint.h>

#define T_DIM 4096
#define B_DIM 16
#define C_DIM 512
#define M_DIM (T_DIM * B_DIM)      // 65536
#define H_DIM 8
#define K_DIM 7
#define PAD_L 3

// ---------------- scratch (no allocations allowed) ----------------
__device__ __align__(16) __half g_yh[(size_t)M_DIM * C_DIM];   // GEMM out (fp16), 64 MB
__device__ __align__(16) __half g_wqh[C_DIM * C_DIM];          // quantized W, fp16 exact
__device__ float g_wsm[H_DIM * K_DIM];                         // softmaxed conv kernels

// ---------------- helpers ----------------
static __device__ __forceinline__ uint32_t smem_u32(const void* p) {
    uint32_t a;
    asm("{ .reg .u64 t; cvta.to.shared.u64 t, %1; cvt.u32.u64 %0, t; }" : "=r"(a) : "l"(p));
    return a;
}

#define CP_ASYNC16(dst, src) \
    asm volatile("cp.async.cg.shared.global [%0], [%1], 16;" :: "r"(dst), "l"(src) : "memory")
#define CP_COMMIT() asm volatile("cp.async.commit_group;" ::: "memory")
#define CP_WAIT1()  asm volatile("cp.async.wait_group 1;" ::: "memory")

#define LDSM_X4(r0, r1, r2, r3, a) \
    asm volatile("ldmatrix.sync.aligned.m8n8.x4.shared.b16 {%0,%1,%2,%3}, [%4];" \
        : "=r"(r0), "=r"(r1), "=r"(r2), "=r"(r3) : "r"(a))

#define MMA_F16(d, a, b0, b1) \
    asm volatile("mma.sync.aligned.m16n8k16.row.col.f32.f16.f16.f32 " \
        "{%0,%1,%2,%3}, {%4,%5,%6,%7}, {%8,%9}, {%0,%1,%2,%3};" \
        : "+f"((d)[0]), "+f"((d)[1]), "+f"((d)[2]), "+f"((d)[3]) \
        : "r"((a)[0]), "r"((a)[1]), "r"((a)[2]), "r"((a)[3]), "r"(b0), "r"(b1))

static __device__ __forceinline__ uint32_t packh2(float a, float b) {
    __half2 h = __floats2half2_rn(a, b);
    return *reinterpret_cast<uint32_t*>(&h);
}

// ---------------- prep: quantize W -> fp16 (exact powers of 2) + softmax ----------------
__global__ void prep_kernel(const float* __restrict__ W,
                            const float* __restrict__ conv_w) {
    int i = blockIdx.x * 256 + threadIdx.x;
    if (i < C_DIM * C_DIM) {
        float w = W[i];
        float a = fabsf(w) + 1e-12f;
        float e = rintf(log2f(a));
        float q = copysignf(exp2f(e), w);
        g_wqh[i] = __float2half((w == 0.0f) ? 0.0f : q);
    }
    if (blockIdx.x == 0 && threadIdx.x < H_DIM) {
        int h = threadIdx.x;
        float v[K_DIM];
        float m = -1e30f;
        #pragma unroll
        for (int k = 0; k < K_DIM; ++k) { v[k] = conv_w[h * K_DIM + k]; m = fmaxf(m, v[k]); }
        float s = 0.0f;
        #pragma unroll
        for (int k = 0; k < K_DIM; ++k) { v[k] = expf(v[k] - m); s += v[k]; }
        float inv = 1.0f / s;
        #pragma unroll
        for (int k = 0; k < K_DIM; ++k) g_wsm[h * K_DIM + k] = v[k] * inv;
    }
}

// ---------------- persistent GEMM: continuous chunk pipeline across tiles ----------------
// CTA tile 128x256, BK=64, 8 warps (2 wm x 4 wn), warp tile 64x64, 3-stage.
#define BM 128
#define BN 256
#define BK 64
#define ST_A 0
#define ST_B 16384
#define ST_SIZE 49152
#define SMEM_GEMM (3 * ST_SIZE)
#define KCH (C_DIM / BK)   // 8 chunks per tile
#define NTILES ((M_DIM / BM) * (C_DIM / BN))   // 1024
#define GRID_P 148

__global__ void __launch_bounds__(256, 1) gemm_mma(const float* __restrict__ x,
                                                   const float* __restrict__ bias) {
    extern __shared__ char sm[];
    const uint32_t sb = smem_u32(sm);
    const int tid = threadIdx.x;
    const int lane = tid & 31;
    const int wid = tid >> 5;
    const int wm = wid & 1;          // warp row 0..1 (64 M rows each)
    const int wn = wid >> 1;         // warp col 0..3 (64 N cols each)
    const int bid = blockIdx.x;

    const int ntiles = (NTILES - bid + GRID_P - 1) / GRID_P;   // 7 or 6
    const int total_chunks = ntiles * KCH;

    float acc[4][8][4];
    #pragma unroll
    for (int i = 0; i < 4; ++i)
        #pragma unroll
        for (int j = 0; j < 8; ++j)
            #pragma unroll
            for (int q = 0; q < 4; ++q) acc[i][j][q] = 0.0f;

    // per-thread load geometry
    int ar[8], ag[8];
    #pragma unroll
    for (int t = 0; t < 8; ++t) { int idx = tid + t * 256; ar[t] = idx >> 4; ag[t] = idx & 15; }

    auto chunk_coords = [&](int j, int& m0, int& n0, int& kt) {
        int tile = bid + (j >> 3) * GRID_P;
        n0 = (tile & 1) * BN;
        m0 = (tile >> 1) * BM;
        kt = (j & 7) * BK;
    };
    auto ldgA = [&](int j, float4* regs) {
        int m0, n0, kt; chunk_coords(j, m0, n0, kt);
        #pragma unroll
        for (int t = 0; t < 8; ++t)
            regs[t] = *(const float4*)&x[(size_t)(m0 + ar[t]) * C_DIM + kt + ag[t] * 4];
    };
    auto storeA = [&](int stage, const float4* regs) {
        const uint32_t base = sb + stage * ST_SIZE + ST_A;
        #pragma unroll
        for (int t = 0; t < 8; ++t) {
            uint32_t d = base + ar[t] * 128 + (((ag[t] >> 1) ^ (ar[t] & 7)) * 16) + (ag[t] & 1) * 8;
            uint2 v = make_uint2(packh2(regs[t].x, regs[t].y), packh2(regs[t].z, regs[t].w));
            asm volatile("st.shared.v2.b32 [%0], {%1, %2};" :: "r"(d), "r"(v.x), "r"(v.y) : "memory");
        }
    };
    auto issueB = [&](int stage, int j) {
        int m0, n0, kt; chunk_coords(j, m0, n0, kt);
        const uint32_t base = sb + stage * ST_SIZE;
        #pragma unroll
        for (int t = 0; t < 8; ++t) {
            int idx = tid + t * 256;
            int r = idx >> 3, c = idx & 7;
            const __half* s = g_wqh + (size_t)(n0 + r) * C_DIM + kt + c * 8;
            uint32_t d = base + ST_B + r * 128 + ((c ^ (r & 7)) * 16);
            CP_ASYNC16(d, s);
        }
    };

    float4 areg[8];
    ldgA(0, areg); storeA(0, areg);
    issueB(0, 0); CP_COMMIT();
    ldgA(1, areg); storeA(1, areg);
    issueB(1, 1); CP_COMMIT();

    // ldmatrix per-lane geometry
    const int arow  = wm * 64 + (lane & 15);
    const int axor  = arow & 7;
    const int ahalf = lane >> 4;
    const int bmidx = lane >> 3;
    const int brow0 = wn * 64 + ((bmidx >> 1) << 3) + (lane & 7);
    const int bxor  = lane & 7;
    const int bko   = bmidx & 1;

    const int r0 = lane >> 2;
    const int c2 = (lane & 3) * 2;

    #pragma unroll 1
    for (int j = 0; j < total_chunks; ++j) {
        const bool pf = (j + 2 < total_chunks);
        if (pf) ldgA(j + 2, areg);      // LDG before the wait: full MMA phase to land
        CP_WAIT1();
        __syncthreads();

        const uint32_t base = sb + (j % 3) * ST_SIZE;
        const uint32_t a_b = base + ST_A + arow * 128;
        const uint32_t b_b = base + ST_B + brow0 * 128;

        #pragma unroll
        for (int ks = 0; ks < 4; ++ks) {
            uint32_t coff = (((ks * 2 + ahalf) ^ axor) * 16);
            uint32_t ah[4][4], bb[4][4];
            #pragma unroll
            for (int mt = 0; mt < 4; ++mt)
                LDSM_X4(ah[mt][0], ah[mt][1], ah[mt][2], ah[mt][3], a_b + mt * 2048 + coff);
            uint32_t bcoff = (((ks * 2 + bko) ^ bxor) * 16);
            #pragma unroll
            for (int np = 0; np < 4; ++np)
                LDSM_X4(bb[np][0], bb[np][1], bb[np][2], bb[np][3], b_b + np * 2048 + bcoff);
            #pragma unroll
            for (int mt = 0; mt < 4; ++mt)
                #pragma unroll
                for (int nt = 0; nt < 8; ++nt) {
                    uint32_t b0 = bb[nt >> 1][(nt & 1) * 2];
                    uint32_t b1 = bb[nt >> 1][(nt & 1) * 2 + 1];
                    MMA_F16(acc[mt][nt], ah[mt], b0, b1);
                }
        }

        if (pf) {
            storeA((j + 2) % 3, areg);   // stage (j+2)%3 == (j-1)%3: consumed last iter
            issueB((j + 2) % 3, j + 2);
        }
        CP_COMMIT();

        if ((j & 7) == 7) {
            // tile finished: epilogue (registers only — overlaps with in-flight loads)
            int m0, n0, kt; chunk_coords(j, m0, n0, kt);
            #pragma unroll
            for (int mt = 0; mt < 4; ++mt) {
                int row = m0 + wm * 64 + mt * 16 + r0;
                #pragma unroll
                for (int nt = 0; nt < 8; ++nt) {
                    int col = n0 + wn * 64 + nt * 8 + c2;
                    float bx = __ldg(&bias[col]);
                    float by = __ldg(&bias[col + 1]);
                    uint32_t v0 = packh2(acc[mt][nt][0] + bx, acc[mt][nt][1] + by);
                    uint32_t v1 = packh2(acc[mt][nt][2] + bx, acc[mt][nt][3] + by);
                    *(uint32_t*)&g_yh[(size_t)row * C_DIM + col] = v0;
                    *(uint32_t*)&g_yh[(size_t)(row + 8) * C_DIM + col] = v1;
                    #pragma unroll
                    for (int q = 0; q < 4; ++q) acc[mt][nt][q] = 0.0f;
                }
            }
        }
    }
}

// ---------------- depthwise conv along time (fp16 in, fp32 out) ----------------
#define TCONV 32

static __device__ __forceinline__ void fma4(float4& o, float w, const float4& c) {
    o.x = fmaf(w, c.x, o.x); o.y = fmaf(w, c.y, o.y);
    o.z = fmaf(w, c.z, o.z); o.w = fmaf(w, c.w, o.w);
}
static __device__ __forceinline__ float4 ld_y4(const uint2* Y, size_t idx) {
    uint2 raw = __ldg(&Y[idx]);
    __half2 h0 = *reinterpret_cast<__half2*>(&raw.x);
    __half2 h1 = *reinterpret_cast<__half2*>(&raw.y);
    float2 f0 = __half22float2(h0);
    float2 f1 = __half22float2(h1);
    return make_float4(f0.x, f0.y, f1.x, f1.y);
}

__global__ void __launch_bounds__(128) conv_kernel(float* __restrict__ out) {
    const int q  = threadIdx.x;
    const int b  = blockIdx.y;
    const int t0 = blockIdx.x * TCONV;
    const int h  = q >> 4;

    float w[K_DIM];
    #pragma unroll
    for (int k = 0; k < K_DIM; ++k) w[k] = g_wsm[h * K_DIM + k];

    const uint2* Y = (const uint2*)g_yh;
    float4* O = (float4*)out;
    const float4 z4 = make_float4(0.f, 0.f, 0.f, 0.f);

    float4 carry[6];
    #pragma unroll
    for (int j = 0; j < 6; ++j) {
        int tt = t0 - PAD_L + j;
        carry[j] = (tt >= 0) ? ld_y4(Y, (size_t)(tt * B_DIM + b) * 128 + q) : z4;
    }

    #pragma unroll
    for (int ch = 0; ch < TCONV / 4; ++ch) {
        const int tb = t0 + ch * 4;
        float4 cmb[10];
        #pragma unroll
        for (int j = 0; j < 6; ++j) cmb[j] = carry[j];
        #pragma unroll
        for (int j = 0; j < 4; ++j) {
            int tt = tb + PAD_L + j;
            cmb[6 + j] = (tt < T_DIM) ? ld_y4(Y, (size_t)(tt * B_DIM + b) * 128 + q) : z4;
        }
        #pragma unroll
        for (int i = 0; i < 4; ++i) {
            float4 o = z4;
            #pragma unroll
            for (int k = 0; k < K_DIM; ++k) fma4(o, w[k], cmb[i + k]);
            O[(size_t)((tb + i) * B_DIM + b) * 128 + q] = o;
        }
        #pragma unroll
        for (int j = 0; j < 6; ++j) carry[j] = cmb[4 + j];
    }
}

// ---------------- launch ----------------
extern "C" void kernel_launch(void* const* d_in, const int* in_sizes, int n_in,
                              void* d_out, int out_size) {
    const float* x       = (const float*)d_in[0];
    const float* shift_W = (const float*)d_in[1];
    const float* shift_b = (const float*)d_in[2];
    const float* weight  = (const float*)d_in[3];
    float* out = (float*)d_out;

    cudaFuncSetAttribute(gemm_mma, cudaFuncAttributeMaxDynamicSharedMemorySize, SMEM_GEMM);

    prep_kernel<<<(C_DIM * C_DIM + 255) / 256, 256>>>(shift_W, weight);

    gemm_mma<<<GRID_P, 256, SMEM_GEMM>>>(x, shift_b);

    dim3 cgrid(T_DIM / TCONV, B_DIM);     // (128, 16)
    conv_kernel<<<cgrid, 128>>>(out);
}

// round 10
// speedup vs baseline: 1.6773x; 1.0016x over previous
#include <cuda_runtime.h>
#include <cuda_fp16.h>
#include <math.h>
#include <stdint.h>

#define T_DIM 4096
#define B_DIM 16
#define C_DIM 512
#define M_DIM (T_DIM * B_DIM)      // 65536
#define H_DIM 8
#define K_DIM 7
#define PAD_L 3

// ---------------- scratch (no allocations allowed) ----------------
__device__ __align__(16) __half g_yh[(size_t)M_DIM * C_DIM];   // GEMM out (fp16), 64 MB
__device__ __align__(16) __half g_wqh[C_DIM * C_DIM];          // quantized W, fp16 exact
__device__ float g_wsm[H_DIM * K_DIM];                         // softmaxed conv kernels

// ---------------- helpers ----------------
static __device__ __forceinline__ uint32_t smem_u32(const void* p) {
    uint32_t a;
    asm("{ .reg .u64 t; cvta.to.shared.u64 t, %1; cvt.u32.u64 %0, t; }" : "=r"(a) : "l"(p));
    return a;
}

#define CP_ASYNC16(dst, src) \
    asm volatile("cp.async.cg.shared.global [%0], [%1], 16;" :: "r"(dst), "l"(src) : "memory")
#define CP_COMMIT() asm volatile("cp.async.commit_group;" ::: "memory")
#define CP_WAIT2()  asm volatile("cp.async.wait_group 2;" ::: "memory")

#define LDSM_X4(r0, r1, r2, r3, a) \
    asm volatile("ldmatrix.sync.aligned.m8n8.x4.shared.b16 {%0,%1,%2,%3}, [%4];" \
        : "=r"(r0), "=r"(r1), "=r"(r2), "=r"(r3) : "r"(a))

#define MMA_F16(d, a, b0, b1) \
    asm volatile("mma.sync.aligned.m16n8k16.row.col.f32.f16.f16.f32 " \
        "{%0,%1,%2,%3}, {%4,%5,%6,%7}, {%8,%9}, {%0,%1,%2,%3};" \
        : "+f"((d)[0]), "+f"((d)[1]), "+f"((d)[2]), "+f"((d)[3]) \
        : "r"((a)[0]), "r"((a)[1]), "r"((a)[2]), "r"((a)[3]), "r"(b0), "r"(b1))

static __device__ __forceinline__ uint32_t packh2(float a, float b) {
    __half2 h = __floats2half2_rn(a, b);
    return *reinterpret_cast<uint32_t*>(&h);
}

// ---------------- prep: quantize W -> fp16 (exact powers of 2) + softmax ----------------
__global__ void prep_kernel(const float* __restrict__ W,
                            const float* __restrict__ conv_w) {
    int i = blockIdx.x * 256 + threadIdx.x;
    if (i < C_DIM * C_DIM) {
        float w = W[i];
        float a = fabsf(w) + 1e-12f;
        float e = rintf(log2f(a));
        float q = copysignf(exp2f(e), w);
        g_wqh[i] = __float2half((w == 0.0f) ? 0.0f : q);
    }
    if (blockIdx.x == 0 && threadIdx.x < H_DIM) {
        int h = threadIdx.x;
        float v[K_DIM];
        float m = -1e30f;
        #pragma unroll
        for (int k = 0; k < K_DIM; ++k) { v[k] = conv_w[h * K_DIM + k]; m = fmaxf(m, v[k]); }
        float s = 0.0f;
        #pragma unroll
        for (int k = 0; k < K_DIM; ++k) { v[k] = expf(v[k] - m); s += v[k]; }
        float inv = 1.0f / s;
        #pragma unroll
        for (int k = 0; k < K_DIM; ++k) g_wsm[h * K_DIM + k] = v[k] * inv;
    }
}

// ---------------- persistent GEMM: 4-stage relaxed pipeline ----------------
// CTA tile 128x256, BK=64, 8 warps (2 wm x 4 wn), warp tile 64x64.
#define BM 128
#define BN 256
#define BK 64
#define ST_A 0
#define ST_B 16384
#define ST_SIZE 49152
#define NSTAGE 4
#define SMEM_GEMM (NSTAGE * ST_SIZE)   // 192 KB
#define KCH (C_DIM / BK)   // 8 chunks per tile
#define NTILES ((M_DIM / BM) * (C_DIM / BN))   // 1024
#define GRID_P 148

__global__ void __launch_bounds__(256, 1) gemm_mma(const float* __restrict__ x,
                                                   const float* __restrict__ bias) {
    extern __shared__ char sm[];
    const uint32_t sb = smem_u32(sm);
    const int tid = threadIdx.x;
    const int lane = tid & 31;
    const int wid = tid >> 5;
    const int wm = wid & 1;          // warp row 0..1 (64 M rows each)
    const int wn = wid >> 1;         // warp col 0..3 (64 N cols each)
    const int bid = blockIdx.x;

    const int ntiles = (NTILES - bid + GRID_P - 1) / GRID_P;   // 7 or 6
    const int total_chunks = ntiles * KCH;

    float acc[4][8][4];
    #pragma unroll
    for (int i = 0; i < 4; ++i)
        #pragma unroll
        for (int j = 0; j < 8; ++j)
            #pragma unroll
            for (int q = 0; q < 4; ++q) acc[i][j][q] = 0.0f;

    // per-thread load geometry
    int ar[8], ag[8];
    #pragma unroll
    for (int t = 0; t < 8; ++t) { int idx = tid + t * 256; ar[t] = idx >> 4; ag[t] = idx & 15; }

    auto chunk_coords = [&](int j, int& m0, int& n0, int& kt) {
        int tile = bid + (j >> 3) * GRID_P;
        n0 = (tile & 1) * BN;
        m0 = (tile >> 1) * BM;
        kt = (j & 7) * BK;
    };
    auto ldgA = [&](int j, float4* regs) {
        int m0, n0, kt; chunk_coords(j, m0, n0, kt);
        #pragma unroll
        for (int t = 0; t < 8; ++t)
            regs[t] = *(const float4*)&x[(size_t)(m0 + ar[t]) * C_DIM + kt + ag[t] * 4];
    };
    auto storeA = [&](int stage, const float4* regs) {
        const uint32_t base = sb + stage * ST_SIZE + ST_A;
        #pragma unroll
        for (int t = 0; t < 8; ++t) {
            uint32_t d = base + ar[t] * 128 + (((ag[t] >> 1) ^ (ar[t] & 7)) * 16) + (ag[t] & 1) * 8;
            uint2 v = make_uint2(packh2(regs[t].x, regs[t].y), packh2(regs[t].z, regs[t].w));
            asm volatile("st.shared.v2.b32 [%0], {%1, %2};" :: "r"(d), "r"(v.x), "r"(v.y) : "memory");
        }
    };
    auto issueB = [&](int stage, int j) {
        int m0, n0, kt; chunk_coords(j, m0, n0, kt);
        const uint32_t base = sb + stage * ST_SIZE;
        #pragma unroll
        for (int t = 0; t < 8; ++t) {
            int idx = tid + t * 256;
            int r = idx >> 3, c = idx & 7;
            const __half* s = g_wqh + (size_t)(n0 + r) * C_DIM + kt + c * 8;
            uint32_t d = base + ST_B + r * 128 + ((c ^ (r & 7)) * 16);
            CP_ASYNC16(d, s);
        }
    };

    // prologue: fill stages 0..2 (A sync, B async; one group per chunk)
    float4 areg[8];
    #pragma unroll
    for (int s = 0; s < 3; ++s) {
        ldgA(s, areg); storeA(s, areg);
        issueB(s, s); CP_COMMIT();
    }

    // ldmatrix per-lane geometry
    const int arow  = wm * 64 + (lane & 15);
    const int axor  = arow & 7;
    const int ahalf = lane >> 4;
    const int bmidx = lane >> 3;
    const int brow0 = wn * 64 + ((bmidx >> 1) << 3) + (lane & 7);
    const int bxor  = lane & 7;
    const int bko   = bmidx & 1;

    const int r0 = lane >> 2;
    const int c2 = (lane & 3) * 2;

    #pragma unroll 1
    for (int j = 0; j < total_chunks; ++j) {
        const bool pf = (j + 3 < total_chunks);
        if (pf) ldgA(j + 3, areg);      // LDG early: full MMA phase to land
        CP_WAIT2();                      // <=2 groups pending => chunk j's B complete
        __syncthreads();
        if (pf) issueB((j + 3) & 3, j + 3);   // stage (j-1)%4: readers done (barrier)
        CP_COMMIT();                     // ALWAYS commit: keeps group counting exact

        const uint32_t base = sb + (j & 3) * ST_SIZE;
        const uint32_t a_b = base + ST_A + arow * 128;
        const uint32_t b_b = base + ST_B + brow0 * 128;

        #pragma unroll
        for (int ks = 0; ks < 4; ++ks) {
            uint32_t coff = (((ks * 2 + ahalf) ^ axor) * 16);
            uint32_t ah[4][4], bb[4][4];
            #pragma unroll
            for (int mt = 0; mt < 4; ++mt)
                LDSM_X4(ah[mt][0], ah[mt][1], ah[mt][2], ah[mt][3], a_b + mt * 2048 + coff);
            uint32_t bcoff = (((ks * 2 + bko) ^ bxor) * 16);
            #pragma unroll
            for (int np = 0; np < 4; ++np)
                LDSM_X4(bb[np][0], bb[np][1], bb[np][2], bb[np][3], b_b + np * 2048 + bcoff);
            #pragma unroll
            for (int mt = 0; mt < 4; ++mt)
                #pragma unroll
                for (int nt = 0; nt < 8; ++nt) {
                    uint32_t b0 = bb[nt >> 1][(nt & 1) * 2];
                    uint32_t b1 = bb[nt >> 1][(nt & 1) * 2 + 1];
                    MMA_F16(acc[mt][nt], ah[mt], b0, b1);
                }
        }

        if (pf) storeA((j + 3) & 3, areg);   // after MMA: LDG long since landed

        if ((j & 7) == 7) {
            // tile finished: epilogue (overlaps with in-flight async loads)
            int m0, n0, kt; chunk_coords(j, m0, n0, kt);
            #pragma unroll
            for (int mt = 0; mt < 4; ++mt) {
                int row = m0 + wm * 64 + mt * 16 + r0;
                #pragma unroll
                for (int nt = 0; nt < 8; ++nt) {
                    int col = n0 + wn * 64 + nt * 8 + c2;
                    float bx = __ldg(&bias[col]);
                    float by = __ldg(&bias[col + 1]);
                    uint32_t v0 = packh2(acc[mt][nt][0] + bx, acc[mt][nt][1] + by);
                    uint32_t v1 = packh2(acc[mt][nt][2] + bx, acc[mt][nt][3] + by);
                    *(uint32_t*)&g_yh[(size_t)row * C_DIM + col] = v0;
                    *(uint32_t*)&g_yh[(size_t)(row + 8) * C_DIM + col] = v1;
                    #pragma unroll
                    for (int q = 0; q < 4; ++q) acc[mt][nt][q] = 0.0f;
                }
            }
        }
    }
}

// ---------------- depthwise conv along time (fp16 in, fp32 out) ----------------
#define TCONV 32

static __device__ __forceinline__ void fma4(float4& o, float w, const float4& c) {
    o.x = fmaf(w, c.x, o.x); o.y = fmaf(w, c.y, o.y);
    o.z = fmaf(w, c.z, o.z); o.w = fmaf(w, c.w, o.w);
}
static __device__ __forceinline__ float4 ld_y4(const uint2* Y, size_t idx) {
    uint2 raw = __ldg(&Y[idx]);
    __half2 h0 = *reinterpret_cast<__half2*>(&raw.x);
    __half2 h1 = *reinterpret_cast<__half2*>(&raw.y);
    float2 f0 = __half22float2(h0);
    float2 f1 = __half22float2(h1);
    return make_float4(f0.x, f0.y, f1.x, f1.y);
}

__global__ void __launch_bounds__(128) conv_kernel(float* __restrict__ out) {
    const int q  = threadIdx.x;
    const int b  = blockIdx.y;
    const int t0 = blockIdx.x * TCONV;
    const int h  = q >> 4;

    float w[K_DIM];
    #pragma unroll
    for (int k = 0; k < K_DIM; ++k) w[k] = g_wsm[h * K_DIM + k];

    const uint2* Y = (const uint2*)g_yh;
    float4* O = (float4*)out;
    const float4 z4 = make_float4(0.f, 0.f, 0.f, 0.f);

    float4 carry[6];
    #pragma unroll
    for (int j = 0; j < 6; ++j) {
        int tt = t0 - PAD_L + j;
        carry[j] = (tt >= 0) ? ld_y4(Y, (size_t)(tt * B_DIM + b) * 128 + q) : z4;
    }

    #pragma unroll
    for (int ch = 0; ch < TCONV / 4; ++ch) {
        const int tb = t0 + ch * 4;
        float4 cmb[10];
        #pragma unroll
        for (int j = 0; j < 6; ++j) cmb[j] = carry[j];
        #pragma unroll
        for (int j = 0; j < 4; ++j) {
            int tt = tb + PAD_L + j;
            cmb[6 + j] = (tt < T_DIM) ? ld_y4(Y, (size_t)(tt * B_DIM + b) * 128 + q) : z4;
        }
        #pragma unroll
        for (int i = 0; i < 4; ++i) {
            float4 o = z4;
            #pragma unroll
            for (int k = 0; k < K_DIM; ++k) fma4(o, w[k], cmb[i + k]);
            O[(size_t)((tb + i) * B_DIM + b) * 128 + q] = o;
        }
        #pragma unroll
        for (int j = 0; j < 6; ++j) carry[j] = cmb[4 + j];
    }
}

// ---------------- launch ----------------
extern "C" void kernel_launch(void* const* d_in, const int* in_sizes, int n_in,
                              void* d_out, int out_size) {
    const float* x       = (const float*)d_in[0];
    const float* shift_W = (const float*)d_in[1];
    const float* shift_b = (const float*)d_in[2];
    const float* weight  = (const float*)d_in[3];
    float* out = (float*)d_out;

    cudaFuncSetAttribute(gemm_mma, cudaFuncAttributeMaxDynamicSharedMemorySize, SMEM_GEMM);

    prep_kernel<<<(C_DIM * C_DIM + 255) / 256, 256>>>(shift_W, weight);

    gemm_mma<<<GRID_P, 256, SMEM_GEMM>>>(x, shift_b);

    dim3 cgrid(T_DIM / TCONV, B_DIM);     // (128, 16)
    conv_kernel<<<cgrid, 128>>>(out);
}

// round 12
// speedup vs baseline: 1.7945x; 1.0699x over previous
#include <cuda_runtime.h>
#include <cuda_fp16.h>
#include <math.h>
#include <stdint.h>

#define T_DIM 4096
#define B_DIM 16
#define C_DIM 512
#define M_DIM (T_DIM * B_DIM)      // 65536
#define H_DIM 8
#define K_DIM 7
#define PAD_L 3

// ---------------- scratch (no allocations allowed) ----------------
__device__ __align__(32) __half g_yh[(size_t)M_DIM * C_DIM];   // GEMM out (fp16), 64 MB
__device__ __align__(16) __half g_wqh[C_DIM * C_DIM];          // quantized W, fp16 exact
__device__ float g_wsm[H_DIM * K_DIM];                         // softmaxed conv kernels

// ---------------- helpers ----------------
static __device__ __forceinline__ uint32_t smem_u32(const void* p) {
    uint32_t a;
    asm("{ .reg .u64 t; cvta.to.shared.u64 t, %1; cvt.u32.u64 %0, t; }" : "=r"(a) : "l"(p));
    return a;
}

#define CP_ASYNC16(dst, src) \
    asm volatile("cp.async.cg.shared.global [%0], [%1], 16;" :: "r"(dst), "l"(src) : "memory")
#define CP_COMMIT() asm volatile("cp.async.commit_group;" ::: "memory")
#define CP_WAIT2()  asm volatile("cp.async.wait_group 2;" ::: "memory")

#define LDSM_X4(r0, r1, r2, r3, a) \
    asm volatile("ldmatrix.sync.aligned.m8n8.x4.shared.b16 {%0,%1,%2,%3}, [%4];" \
        : "=r"(r0), "=r"(r1), "=r"(r2), "=r"(r3) : "r"(a))

#define MMA_F16(d, a, b0, b1) \
    asm volatile("mma.sync.aligned.m16n8k16.row.col.f32.f16.f16.f32 " \
        "{%0,%1,%2,%3}, {%4,%5,%6,%7}, {%8,%9}, {%0,%1,%2,%3};" \
        : "+f"((d)[0]), "+f"((d)[1]), "+f"((d)[2]), "+f"((d)[3]) \
        : "r"((a)[0]), "r"((a)[1]), "r"((a)[2]), "r"((a)[3]), "r"(b0), "r"(b1))

static __device__ __forceinline__ uint32_t packh2(float a, float b) {
    __half2 h = __floats2half2_rn(a, b);
    return *reinterpret_cast<uint32_t*>(&h);
}

// 256-bit L2-hinted ops (the only widths ptxas accepts hints on for this target)
static __device__ __forceinline__ void ldg_ef_8f(const float* p, float* v) {
    asm volatile("ld.global.nc.L2::evict_first.v8.b32 {%0,%1,%2,%3,%4,%5,%6,%7}, [%8];"
        : "=f"(v[0]), "=f"(v[1]), "=f"(v[2]), "=f"(v[3]),
          "=f"(v[4]), "=f"(v[5]), "=f"(v[6]), "=f"(v[7]) : "l"(p));
}
static __device__ __forceinline__ void stg_ef_8f(void* p, const float* v) {
    asm volatile("st.global.L2::evict_first.v8.b32 [%0], {%1,%2,%3,%4,%5,%6,%7,%8};"
        :: "l"(p), "f"(v[0]), "f"(v[1]), "f"(v[2]), "f"(v[3]),
           "f"(v[4]), "f"(v[5]), "f"(v[6]), "f"(v[7]) : "memory");
}

// ---------------- prep: quantize W -> fp16 (exact powers of 2) + softmax ----------------
__global__ void prep_kernel(const float* __restrict__ W,
                            const float* __restrict__ conv_w) {
    int i = blockIdx.x * 256 + threadIdx.x;
    if (i < C_DIM * C_DIM) {
        float w = W[i];
        float a = fabsf(w) + 1e-12f;
        float e = rintf(log2f(a));
        float q = copysignf(exp2f(e), w);
        g_wqh[i] = __float2half((w == 0.0f) ? 0.0f : q);
    }
    if (blockIdx.x == 0 && threadIdx.x < H_DIM) {
        int h = threadIdx.x;
        float v[K_DIM];
        float m = -1e30f;
        #pragma unroll
        for (int k = 0; k < K_DIM; ++k) { v[k] = conv_w[h * K_DIM + k]; m = fmaxf(m, v[k]); }
        float s = 0.0f;
        #pragma unroll
        for (int k = 0; k < K_DIM; ++k) { v[k] = expf(v[k] - m); s += v[k]; }
        float inv = 1.0f / s;
        #pragma unroll
        for (int k = 0; k < K_DIM; ++k) g_wsm[h * K_DIM + k] = v[k] * inv;
    }
}

// ---------------- persistent GEMM: 4-stage pipeline, evict_first x reads ----------------
// CTA tile 128x256, BK=64, 8 warps (2 wm x 4 wn), warp tile 64x64.
#define BM 128
#define BN 256
#define BK 64
#define ST_A 0
#define ST_B 16384
#define ST_SIZE 49152
#define NSTAGE 4
#define SMEM_GEMM (NSTAGE * ST_SIZE)   // 192 KB
#define KCH (C_DIM / BK)   // 8 chunks per tile
#define NTILES ((M_DIM / BM) * (C_DIM / BN))   // 1024
#define GRID_P 148

__global__ void __launch_bounds__(256, 1) gemm_mma(const float* __restrict__ x,
                                                   const float* __restrict__ bias) {
    extern __shared__ char sm[];
    const uint32_t sb = smem_u32(sm);
    const int tid = threadIdx.x;
    const int lane = tid & 31;
    const int wid = tid >> 5;
    const int wm = wid & 1;          // warp row 0..1 (64 M rows each)
    const int wn = wid >> 1;         // warp col 0..3 (64 N cols each)
    const int bid = blockIdx.x;

    const int ntiles = (NTILES - bid + GRID_P - 1) / GRID_P;   // 7 or 6
    const int total_chunks = ntiles * KCH;

    float acc[4][8][4];
    #pragma unroll
    for (int i = 0; i < 4; ++i)
        #pragma unroll
        for (int j = 0; j < 8; ++j)
            #pragma unroll
            for (int q = 0; q < 4; ++q) acc[i][j][q] = 0.0f;

    // A: 128 rows x 8 groups(32B) per stage = 1024 ops, 4/thread (v8 LDG)
    int ar[4], ac[4];
    #pragma unroll
    for (int t = 0; t < 4; ++t) { int idx = tid + t * 256; ar[t] = idx >> 3; ac[t] = idx & 7; }

    auto chunk_coords = [&](int j, int& m0, int& n0, int& kt) {
        int tile = bid + (j >> 3) * GRID_P;
        n0 = (tile & 1) * BN;
        m0 = (tile >> 1) * BM;
        kt = (j & 7) * BK;
    };
    auto ldgA = [&](int j, float* regs) {   // regs: 4 x 8 floats
        int m0, n0, kt; chunk_coords(j, m0, n0, kt);
        #pragma unroll
        for (int t = 0; t < 4; ++t)
            ldg_ef_8f(&x[(size_t)(m0 + ar[t]) * C_DIM + kt + ac[t] * 8], regs + t * 8);
    };
    auto storeA = [&](int stage, const float* regs) {
        const uint32_t base = sb + stage * ST_SIZE + ST_A;
        #pragma unroll
        for (int t = 0; t < 4; ++t) {
            const float* r = regs + t * 8;
            uint32_t d = base + ar[t] * 128 + ((ac[t] ^ (ar[t] & 7)) * 16);
            uint32_t p0 = packh2(r[0], r[1]), p1 = packh2(r[2], r[3]);
            uint32_t p2 = packh2(r[4], r[5]), p3 = packh2(r[6], r[7]);
            asm volatile("st.shared.v4.b32 [%0], {%1, %2, %3, %4};"
                :: "r"(d), "r"(p0), "r"(p1), "r"(p2), "r"(p3) : "memory");
        }
    };
    auto issueB = [&](int stage, int j) {
        int m0, n0, kt; chunk_coords(j, m0, n0, kt);
        const uint32_t base = sb + stage * ST_SIZE;
        #pragma unroll
        for (int t = 0; t < 8; ++t) {
            int idx = tid + t * 256;
            int r = idx >> 3, c = idx & 7;
            const __half* s = g_wqh + (size_t)(n0 + r) * C_DIM + kt + c * 8;
            uint32_t d = base + ST_B + r * 128 + ((c ^ (r & 7)) * 16);
            CP_ASYNC16(d, s);
        }
    };

    // prologue: fill stages 0..2
    float areg[32];
    #pragma unroll
    for (int s = 0; s < 3; ++s) {
        ldgA(s, areg); storeA(s, areg);
        issueB(s, s); CP_COMMIT();
    }

    const int arow  = wm * 64 + (lane & 15);
    const int axor  = arow & 7;
    const int ahalf = lane >> 4;
    const int bmidx = lane >> 3;
    const int brow0 = wn * 64 + ((bmidx >> 1) << 3) + (lane & 7);
    const int bxor  = lane & 7;
    const int bko   = bmidx & 1;

    const int r0 = lane >> 2;
    const int c2 = (lane & 3) * 2;

    #pragma unroll 1
    for (int j = 0; j < total_chunks; ++j) {
        const bool pf = (j + 3 < total_chunks);
        if (pf) ldgA(j + 3, areg);
        CP_WAIT2();
        __syncthreads();
        if (pf) issueB((j + 3) & 3, j + 3);
        CP_COMMIT();

        const uint32_t base = sb + (j & 3) * ST_SIZE;
        const uint32_t a_b = base + ST_A + arow * 128;
        const uint32_t b_b = base + ST_B + brow0 * 128;

        #pragma unroll
        for (int ks = 0; ks < 4; ++ks) {
            uint32_t coff = (((ks * 2 + ahalf) ^ axor) * 16);
            uint32_t ah[4][4], bb[4][4];
            #pragma unroll
            for (int mt = 0; mt < 4; ++mt)
                LDSM_X4(ah[mt][0], ah[mt][1], ah[mt][2], ah[mt][3], a_b + mt * 2048 + coff);
            uint32_t bcoff = (((ks * 2 + bko) ^ bxor) * 16);
            #pragma unroll
            for (int np = 0; np < 4; ++np)
                LDSM_X4(bb[np][0], bb[np][1], bb[np][2], bb[np][3], b_b + np * 2048 + bcoff);
            #pragma unroll
            for (int mt = 0; mt < 4; ++mt)
                #pragma unroll
                for (int nt = 0; nt < 8; ++nt) {
                    uint32_t b0 = bb[nt >> 1][(nt & 1) * 2];
                    uint32_t b1 = bb[nt >> 1][(nt & 1) * 2 + 1];
                    MMA_F16(acc[mt][nt], ah[mt], b0, b1);
                }
        }

        if (pf) storeA((j + 3) & 3, areg);

        if ((j & 7) == 7) {
            // tile epilogue: y keeps default L2 policy (stays resident for conv)
            int m0, n0, kt; chunk_coords(j, m0, n0, kt);
            #pragma unroll
            for (int mt = 0; mt < 4; ++mt) {
                int row = m0 + wm * 64 + mt * 16 + r0;
                #pragma unroll
                for (int nt = 0; nt < 8; ++nt) {
                    int col = n0 + wn * 64 + nt * 8 + c2;
                    float bx = __ldg(&bias[col]);
                    float by = __ldg(&bias[col + 1]);
                    uint32_t v0 = packh2(acc[mt][nt][0] + bx, acc[mt][nt][1] + by);
                    uint32_t v1 = packh2(acc[mt][nt][2] + bx, acc[mt][nt][3] + by);
                    *(uint32_t*)&g_yh[(size_t)row * C_DIM + col] = v0;
                    *(uint32_t*)&g_yh[(size_t)(row + 8) * C_DIM + col] = v1;
                    #pragma unroll
                    for (int q = 0; q < 4; ++q) acc[mt][nt][q] = 0.0f;
                }
            }
        }
    }
}

// ---------------- depthwise conv: 8 ch/thread, 32B evict_first out stores ----------------
#define TCONV 32

struct f8 { float v[8]; };

static __device__ __forceinline__ f8 ld_y8(const uint4* Y, size_t idx) {
    uint4 raw = __ldg(&Y[idx]);       // default policy: last use, L2-resident hit
    f8 o;
    __half2* h = reinterpret_cast<__half2*>(&raw);
    #pragma unroll
    for (int i = 0; i < 4; ++i) {
        float2 f = __half22float2(h[i]);
        o.v[i * 2] = f.x; o.v[i * 2 + 1] = f.y;
    }
    return o;
}

__global__ void __launch_bounds__(128) conv_kernel(float* __restrict__ out) {
    const int q8 = threadIdx.x & 63;          // 8-channel group: channels q8*8..q8*8+7
    const int b  = blockIdx.y * 2 + (threadIdx.x >> 6);
    const int t0 = blockIdx.x * TCONV;
    const int h  = q8 >> 3;                   // (q8*8)/64

    float w[K_DIM];
    #pragma unroll
    for (int k = 0; k < K_DIM; ++k) w[k] = g_wsm[h * K_DIM + k];

    const uint4* Y = (const uint4*)g_yh;      // (t*16+b)*64 + q8
    const f8 z8 = {};

    f8 carry[6];
    #pragma unroll
    for (int j = 0; j < 6; ++j) {
        int tt = t0 - PAD_L + j;
        carry[j] = (tt >= 0) ? ld_y8(Y, (size_t)(tt * B_DIM + b) * 64 + q8) : z8;
    }

    #pragma unroll
    for (int ch = 0; ch < TCONV / 4; ++ch) {
        const int tb = t0 + ch * 4;
        f8 cmb[10];
        #pragma unroll
        for (int j = 0; j < 6; ++j) cmb[j] = carry[j];
        #pragma unroll
        for (int j = 0; j < 4; ++j) {
            int tt = tb + PAD_L + j;
            cmb[6 + j] = (tt < T_DIM) ? ld_y8(Y, (size_t)(tt * B_DIM + b) * 64 + q8) : z8;
        }
        #pragma unroll
        for (int i = 0; i < 4; ++i) {
            f8 o = z8;
            #pragma unroll
            for (int k = 0; k < K_DIM; ++k)
                #pragma unroll
                for (int e = 0; e < 8; ++e)
                    o.v[e] = fmaf(w[k], cmb[i + k].v[e], o.v[e]);
            stg_ef_8f(&out[(size_t)((tb + i) * B_DIM + b) * C_DIM + q8 * 8], o.v);
        }
        #pragma unroll
        for (int j = 0; j < 6; ++j) carry[j] = cmb[4 + j];
    }
}

// ---------------- launch ----------------
extern "C" void kernel_launch(void* const* d_in, const int* in_sizes, int n_in,
                              void* d_out, int out_size) {
    const float* x       = (const float*)d_in[0];
    const float* shift_W = (const float*)d_in[1];
    const float* shift_b = (const float*)d_in[2];
    const float* weight  = (const float*)d_in[3];
    float* out = (float*)d_out;

    cudaFuncSetAttribute(gemm_mma, cudaFuncAttributeMaxDynamicSharedMemorySize, SMEM_GEMM);

    prep_kernel<<<(C_DIM * C_DIM + 255) / 256, 256>>>(shift_W, weight);

    gemm_mma<<<GRID_P, 256, SMEM_GEMM>>>(x, shift_b);

    dim3 cgrid(T_DIM / TCONV, B_DIM / 2);     // (128, 8)
    conv_kernel<<<cgrid, 128>>>(out);
}